// round 1
// baseline (speedup 1.0000x reference)
#include <cuda_runtime.h>
#include <math.h>

// Problem constants
// B=1, C=256, S=64 (M=4096 tokens), H=32, W=128, BLOCKS=2, HEADS=8, DH=32
#define MTOK 4096
#define CDIM 256
#define NCTX 64
#define ATTN_SCALE 0.17677669529663687f  // 32^-0.5

// ---------------- scratch (__device__ globals, no allocation) ----------------
__device__ float g_Xn[4096 * 256];     // normalized grd_x columns
__device__ float g_Wcat[256 * 1024];   // folded [Wk0'|Wv0'|Wk1'|Wv1']
__device__ float g_bcat[1024];         // folded LN-bias contribution
__device__ float g_KV[4096 * 1024];    // K/V for all blocks, per distinct column
__device__ float g_x[4096 * 256];      // running token state
__device__ float g_t[4096 * 256];      // LN_q output
__device__ float g_q[4096 * 256];
__device__ float g_a[4096 * 256];
__device__ float g_z1[4096 * 256];
__device__ float g_z2[4096 * 256];
__device__ float g_h[4096 * 512];
__device__ float g_z3[4096 * 256];
__device__ float g_inv[4096];
__device__ int   g_jL[4096];
__device__ int   g_jR[4096];

// ---------------- helpers ----------------
__device__ __forceinline__ float blockReduceSum256(float v, volatile float* sh) {
    __syncthreads();
#pragma unroll
    for (int o = 16; o; o >>= 1) v += __shfl_xor_sync(0xffffffffu, v, o);
    int tid = threadIdx.x;
    if ((tid & 31) == 0) sh[tid >> 5] = v;
    __syncthreads();
    if (tid == 0) {
        float s = 0.f;
#pragma unroll
        for (int i = 0; i < 8; i++) s += sh[i];
        sh[0] = s;
    }
    __syncthreads();
    return sh[0];
}

// ---------------- small prep kernels ----------------
__global__ void idx_kernel(const float* __restrict__ u, int* __restrict__ jL,
                           int* __restrict__ jR) {
    int m = blockIdx.x * 256 + threadIdx.x;
    float uf = floorf(u[m]);
    jL[m] = (int)fminf(fmaxf(uf, 0.f), 127.f);
    jR[m] = (int)fminf(fmaxf(uf + 1.f, 0.f), 127.f);
}

// normalize column j (over C=256) of grd_x (C, H*W=4096); plain LN (weights folded later)
__global__ __launch_bounds__(256) void colnorm_kernel(const float* __restrict__ gx,
                                                      float* __restrict__ Xn) {
    __shared__ float sh[8];
    int j = blockIdx.x, tid = threadIdx.x;
    float v = gx[tid * 4096 + j];
    float mean = blockReduceSum256(v, sh) * (1.f / 256.f);
    float d = v - mean;
    float var = blockReduceSum256(d * d, sh) * (1.f / 256.f);
    Xn[j * 256 + tid] = d * rsqrtf(var + 1e-5f);
}

// Wcat[c][o], o = [k0|v0|k1|v1] each 256 wide; scale row c by ln weight
__global__ void fold_w_kernel(const float* __restrict__ Wk, const float* __restrict__ Wv,
                              const float* __restrict__ lnkw, const float* __restrict__ lnvw,
                              float* __restrict__ Wcat) {
    int idx = blockIdx.x * 256 + threadIdx.x;   // 256*1024 total
    int c = idx >> 10, o = idx & 1023;
    int seg = o >> 8, i = seg >> 1, isv = seg & 1;
    const float* W = isv ? Wv : Wk;
    float s = (isv ? lnvw : lnkw)[i * 256 + c];
    Wcat[idx] = s * W[(i * 256 + c) * 256 + (o & 255)];
}

// bcat[o] = sum_c ln_b[c] * W[c][o]
__global__ void fold_b_kernel(const float* __restrict__ Wk, const float* __restrict__ Wv,
                              const float* __restrict__ lnkb, const float* __restrict__ lnvb,
                              float* __restrict__ bcat) {
    int o = blockIdx.x * 256 + threadIdx.x;     // 1024 total
    int seg = o >> 8, i = seg >> 1, isv = seg & 1, oo = o & 255;
    const float* W = (isv ? Wv : Wk) + i * 256 * 256;
    const float* b = (isv ? lnvb : lnkb) + i * 256;
    float s = 0.f;
    for (int c = 0; c < 256; c++) s += b[c] * W[c * 256 + oo];
    bcat[o] = s;
}

// LayerNorm over C=256, one row per block
__global__ __launch_bounds__(256) void ln_kernel(const float* __restrict__ in,
                                                 const float* __restrict__ w,
                                                 const float* __restrict__ b,
                                                 float* __restrict__ out) {
    __shared__ float sh[8];
    int m = blockIdx.x, tid = threadIdx.x;
    float v = in[m * 256 + tid];
    float mean = blockReduceSum256(v, sh) * (1.f / 256.f);
    float d = v - mean;
    float var = blockReduceSum256(d * d, sh) * (1.f / 256.f);
    out[m * 256 + tid] = d * rsqrtf(var + 1e-5f) * w[tid] + b[tid];
}

__global__ __launch_bounds__(256) void invnorm_kernel(const float* __restrict__ x,
                                                      float* __restrict__ inv) {
    __shared__ float sh[8];
    int m = blockIdx.x, tid = threadIdx.x;
    float v = x[m * 256 + tid];
    float s2 = blockReduceSum256(v * v, sh);
    if (tid == 0) inv[m] = 1.f / fmaxf(sqrtf(s2), 1e-12f);
}

// tiled transpose: in (R, Cd) -> out (Cd, R), optional per-in-row scale
__global__ void transpose_scale(const float* __restrict__ in, float* __restrict__ out,
                                int R, int Cd, const float* __restrict__ scale) {
    __shared__ float t[32][33];
    int bx = blockIdx.x * 32;   // along Cd
    int by = blockIdx.y * 32;   // along R
    int x = threadIdx.x, y0 = threadIdx.y;
    for (int yy = y0; yy < 32; yy += 8) {
        float s = scale ? scale[by + yy] : 1.f;
        t[yy][x] = in[(by + yy) * Cd + bx + x] * s;
    }
    __syncthreads();
    for (int yy = y0; yy < 32; yy += 8)
        out[(bx + yy) * R + by + x] = t[x][yy];
}

// ---------------- SGEMM: C = A(MxK) @ B(KxN) [+bias] [+gelu | +resid] ----------------
// EPI: 0 = (+bias if non-null), 1 = bias+exact-GELU, 2 = bias+residual
template <int EPI>
__global__ __launch_bounds__(256) void sgemm64(const float* __restrict__ A,
                                               const float* __restrict__ B,
                                               const float* __restrict__ bias,
                                               const float* __restrict__ resid,
                                               float* __restrict__ C,
                                               int M, int N, int K) {
    __shared__ float As[16][64];
    __shared__ float Bs[16][64];
    int tid = threadIdx.x;
    int m0 = blockIdx.y << 6, n0 = blockIdx.x << 6;
    int tx = tid & 15, ty = tid >> 4;
    int arow = tid >> 2, acol = (tid & 3) << 2;
    int brow = tid >> 4, bcol = (tid & 15) << 2;
    const float* Aptr = A + (m0 + arow) * K + acol;
    const float* Bptr = B + brow * N + n0 + bcol;
    float acc[4][4] = {};
    for (int k0 = 0; k0 < K; k0 += 16) {
        float4 av = *(const float4*)(Aptr + k0);
        As[acol + 0][arow] = av.x;
        As[acol + 1][arow] = av.y;
        As[acol + 2][arow] = av.z;
        As[acol + 3][arow] = av.w;
        float4 bv = *(const float4*)(Bptr + (size_t)k0 * N);
        *(float4*)(&Bs[brow][bcol]) = bv;
        __syncthreads();
#pragma unroll
        for (int kk = 0; kk < 16; kk++) {
            float4 a4 = *(const float4*)(&As[kk][ty << 2]);
            float4 b4 = *(const float4*)(&Bs[kk][tx << 2]);
            float ar[4] = {a4.x, a4.y, a4.z, a4.w};
            float br[4] = {b4.x, b4.y, b4.z, b4.w};
#pragma unroll
            for (int i = 0; i < 4; i++)
#pragma unroll
                for (int j = 0; j < 4; j++)
                    acc[i][j] = fmaf(ar[i], br[j], acc[i][j]);
        }
        __syncthreads();
    }
#pragma unroll
    for (int i = 0; i < 4; i++) {
        int m = m0 + (ty << 2) + i;
#pragma unroll
        for (int j = 0; j < 4; j++) {
            int n = n0 + (tx << 2) + j;
            float v = acc[i][j];
            if (bias) v += bias[n];
            if (EPI == 1) v = 0.5f * v * (1.f + erff(v * 0.70710678118654752f));
            if (EPI == 2) v += resid[m * N + n];
            C[m * N + n] = v;
        }
    }
}

// ---------------- attention: warp-per-head, gather K/V by column index ----------------
// q: (4096,256) already LN'd+projected; KV: (4096 cols, 1024) = [k0|v0|k1|v1]
__global__ __launch_bounds__(256) void attn_kernel(const float* __restrict__ q,
                                                   const float* __restrict__ KV,
                                                   const int* __restrict__ jLarr,
                                                   const int* __restrict__ jRarr,
                                                   int kvOff,   // 0 or 512
                                                   float* __restrict__ out) {
    int m = blockIdx.x;
    int h = threadIdx.x >> 5;
    int lane = threadIdx.x & 31;
    int jL = jLarr[m], jR = jRarr[m];
    float qv = q[m * 256 + h * 32 + lane] * ATTN_SCALE;
    int base = kvOff + h * 32 + lane;
    float d0 = 0.f, d1 = 0.f;
#pragma unroll
    for (int n = 0; n < 64; n++) {
        int w = (n < 32) ? jL : jR;
        int j = ((n & 31) << 7) + w;
        float p = KV[j * 1024 + base] * qv;
        p += __shfl_xor_sync(0xffffffffu, p, 16);
        p += __shfl_xor_sync(0xffffffffu, p, 8);
        p += __shfl_xor_sync(0xffffffffu, p, 4);
        p += __shfl_xor_sync(0xffffffffu, p, 2);
        p += __shfl_xor_sync(0xffffffffu, p, 1);
        if (lane == (n & 31)) { if (n < 32) d0 = p; else d1 = p; }
    }
    // softmax over 64 (d0 = n=lane, d1 = n=lane+32)
    float mx = fmaxf(d0, d1);
#pragma unroll
    for (int o = 16; o; o >>= 1) mx = fmaxf(mx, __shfl_xor_sync(0xffffffffu, mx, o));
    float e0 = expf(d0 - mx), e1 = expf(d1 - mx);
    float s = e0 + e1;
#pragma unroll
    for (int o = 16; o; o >>= 1) s += __shfl_xor_sync(0xffffffffu, s, o);
    float invs = 1.f / s;
    float p0 = e0 * invs, p1 = e1 * invs;
    // attn @ V
    float acc = 0.f;
#pragma unroll
    for (int n = 0; n < 64; n++) {
        float pn = __shfl_sync(0xffffffffu, (n < 32) ? p0 : p1, n & 31);
        int w = (n < 32) ? jL : jR;
        int j = ((n & 31) << 7) + w;
        acc += pn * KV[j * 1024 + base + 256];
    }
    out[m * 256 + h * 32 + lane] = acc;
}

// ---------------- host launch ----------------
extern "C" void kernel_launch(void* const* d_in, const int* in_sizes, int n_in,
                              void* d_out, int out_size) {
    (void)in_sizes; (void)n_in; (void)out_size;
    const float* grd2sat = (const float*)d_in[0];
    const float* grd_x   = (const float*)d_in[1];
    const float* u       = (const float*)d_in[2];
    const float* ln_q_w  = (const float*)d_in[3];
    const float* ln_q_b  = (const float*)d_in[4];
    const float* ln_k_w  = (const float*)d_in[5];
    const float* ln_k_b  = (const float*)d_in[6];
    const float* ln_v_w  = (const float*)d_in[7];
    const float* ln_v_b  = (const float*)d_in[8];
    const float* Wq      = (const float*)d_in[9];
    const float* Wk      = (const float*)d_in[10];
    const float* Wv      = (const float*)d_in[11];
    const float* Wproj   = (const float*)d_in[12];
    const float* bproj   = (const float*)d_in[13];
    const float* ln_pre_w  = (const float*)d_in[14];
    const float* ln_pre_b  = (const float*)d_in[15];
    const float* Wm1     = (const float*)d_in[16];
    const float* bm1     = (const float*)d_in[17];
    const float* Wm2     = (const float*)d_in[18];
    const float* bm2     = (const float*)d_in[19];
    const float* ln_post_w = (const float*)d_in[20];
    const float* ln_post_b = (const float*)d_in[21];
    float* out = (float*)d_out;

    float *Xn, *Wcat, *bcat, *KV, *x, *t, *q, *a, *z1, *z2, *hbuf, *z3, *inv;
    int *jL, *jR;
    cudaGetSymbolAddress((void**)&Xn, g_Xn);
    cudaGetSymbolAddress((void**)&Wcat, g_Wcat);
    cudaGetSymbolAddress((void**)&bcat, g_bcat);
    cudaGetSymbolAddress((void**)&KV, g_KV);
    cudaGetSymbolAddress((void**)&x, g_x);
    cudaGetSymbolAddress((void**)&t, g_t);
    cudaGetSymbolAddress((void**)&q, g_q);
    cudaGetSymbolAddress((void**)&a, g_a);
    cudaGetSymbolAddress((void**)&z1, g_z1);
    cudaGetSymbolAddress((void**)&z2, g_z2);
    cudaGetSymbolAddress((void**)&hbuf, g_h);
    cudaGetSymbolAddress((void**)&z3, g_z3);
    cudaGetSymbolAddress((void**)&inv, g_inv);
    cudaGetSymbolAddress((void**)&jL, g_jL);
    cudaGetSymbolAddress((void**)&jR, g_jR);

    // prep
    idx_kernel<<<16, 256>>>(u, jL, jR);
    colnorm_kernel<<<4096, 256>>>(grd_x, Xn);
    fold_w_kernel<<<1024, 256>>>(Wk, Wv, ln_k_w, ln_v_w, Wcat);
    fold_b_kernel<<<4, 256>>>(Wk, Wv, ln_k_b, ln_v_b, bcat);
    // KV = Xn @ Wcat + bcat : (4096 x 1024)
    sgemm64<0><<<dim3(1024 / 64, 4096 / 64), 256>>>(Xn, Wcat, bcat, nullptr, KV,
                                                    4096, 1024, 256);
    // x = grd2sat^T : (4096, 256)
    transpose_scale<<<dim3(4096 / 32, 256 / 32), dim3(32, 8)>>>(grd2sat, x, 256, 4096,
                                                                nullptr);

    for (int i = 0; i < 2; i++) {
        const float* Wq_i = Wq + i * 256 * 256;
        const float* Wp_i = Wproj + i * 256 * 256;
        const float* Wm1_i = Wm1 + i * 256 * 512;
        const float* Wm2_i = Wm2 + i * 512 * 256;
        ln_kernel<<<4096, 256>>>(x, ln_q_w + i * 256, ln_q_b + i * 256, t);
        sgemm64<0><<<dim3(256 / 64, 4096 / 64), 256>>>(t, Wq_i, nullptr, nullptr, q,
                                                       4096, 256, 256);
        attn_kernel<<<4096, 256>>>(q, KV, jL, jR, i * 512, a);
        sgemm64<0><<<dim3(256 / 64, 4096 / 64), 256>>>(a, Wp_i, bproj + i * 256,
                                                       nullptr, z1, 4096, 256, 256);
        ln_kernel<<<4096, 256>>>(z1, ln_pre_w + i * 256, ln_pre_b + i * 256, z2);
        sgemm64<1><<<dim3(512 / 64, 4096 / 64), 256>>>(z2, Wm1_i, bm1 + i * 512,
                                                       nullptr, hbuf, 4096, 512, 256);
        sgemm64<2><<<dim3(256 / 64, 4096 / 64), 256>>>(hbuf, Wm2_i, bm2 + i * 256, z2,
                                                       z3, 4096, 256, 512);
        ln_kernel<<<4096, 256>>>(z3, ln_post_w + i * 256, ln_post_b + i * 256, x);
    }

    // final L2 normalize over C and transpose to (C, S*S)
    invnorm_kernel<<<4096, 256>>>(x, inv);
    transpose_scale<<<dim3(256 / 32, 4096 / 32), dim3(32, 8)>>>(x, out, 4096, 256, inv);
}

// round 3
// speedup vs baseline: 1.1337x; 1.1337x over previous
#include <cuda_runtime.h>
#include <cuda_bf16.h>
#include <math.h>
#include <stdint.h>

#define ATTN_SCALE 0.17677669529663687f  // 32^-0.5

__device__ __forceinline__ uint32_t smem_u32(const void* p) {
    uint32_t a;
    asm("{ .reg .u64 t; cvta.to.shared.u64 t, %1; cvt.u32.u64 %0, t; }" : "=r"(a) : "l"(p));
    return a;
}
__device__ __forceinline__ void cp16(uint32_t s, const void* g) {
    asm volatile("cp.async.cg.shared.global [%0], [%1], 16;" :: "r"(s), "l"(g));
}
__device__ __forceinline__ void cp_commit() { asm volatile("cp.async.commit_group;"); }
__device__ __forceinline__ void cp_wait1() { asm volatile("cp.async.wait_group 1;"); }
__device__ __forceinline__ void ldsm4(uint32_t r[4], uint32_t addr) {
    asm volatile("ldmatrix.sync.aligned.m8n8.x4.shared.b16 {%0,%1,%2,%3}, [%4];"
                 : "=r"(r[0]), "=r"(r[1]), "=r"(r[2]), "=r"(r[3]) : "r"(addr));
}
__device__ __forceinline__ void mma16816(float c[4], const uint32_t a[4], uint32_t b0,
                                         uint32_t b1) {
    asm volatile(
        "mma.sync.aligned.m16n8k16.row.col.f32.bf16.bf16.f32 "
        "{%0,%1,%2,%3}, {%4,%5,%6,%7}, {%8,%9}, {%0,%1,%2,%3};"
        : "+f"(c[0]), "+f"(c[1]), "+f"(c[2]), "+f"(c[3])
        : "r"(a[0]), "r"(a[1]), "r"(a[2]), "r"(a[3]), "r"(b0), "r"(b1));
}
__device__ __forceinline__ void split_bf16(float v, __nv_bfloat16& hi, __nv_bfloat16& lo) {
    hi = __float2bfloat16(v);
    lo = __float2bfloat16(v - __bfloat162float(hi));
}

// =================== device scratch ===================
__device__ __nv_bfloat16 g_Xncat[4096 * 768];
__device__ __nv_bfloat16 g_Wkvcat[1024 * 768];
__device__ float g_bcat[1024];
__device__ float g_KV[4096 * 1024];
__device__ float g_x[4096 * 256];
__device__ __nv_bfloat16 g_tcat[4096 * 768];
__device__ float g_q[4096 * 256];
__device__ __nv_bfloat16 g_acat[4096 * 768];
__device__ float g_z1[4096 * 256];
__device__ float g_z2[4096 * 256];
__device__ __nv_bfloat16 g_z2cat[4096 * 768];
__device__ __nv_bfloat16 g_hcat[4096 * 1536];
__device__ float g_z3[4096 * 256];
__device__ __nv_bfloat16 g_Wqcat[256 * 768];
__device__ __nv_bfloat16 g_Wpcat[256 * 768];
__device__ __nv_bfloat16 g_Wm1cat[512 * 768];
__device__ __nv_bfloat16 g_Wm2cat[256 * 1536];
__device__ float g_inv[4096];
__device__ int g_jL[4096], g_jR[4096];

// =================== block reduce helper ===================
__device__ __forceinline__ float blockReduceSum256(float v, volatile float* sh) {
    __syncthreads();
#pragma unroll
    for (int o = 16; o; o >>= 1) v += __shfl_xor_sync(0xffffffffu, v, o);
    int tid = threadIdx.x;
    if ((tid & 31) == 0) sh[tid >> 5] = v;
    __syncthreads();
    if (tid == 0) {
        float s = 0.f;
#pragma unroll
        for (int i = 0; i < 8; i++) s += sh[i];
        sh[0] = s;
    }
    __syncthreads();
    return sh[0];
}

// =================== small prep kernels ===================
__global__ void idx_kernel(const float* __restrict__ u, int* __restrict__ jL,
                           int* __restrict__ jR) {
    int m = blockIdx.x * 256 + threadIdx.x;
    float uf = floorf(u[m]);
    jL[m] = (int)fminf(fmaxf(uf, 0.f), 127.f);
    jR[m] = (int)fminf(fmaxf(uf + 1.f, 0.f), 127.f);
}

__global__ __launch_bounds__(256) void colnorm_kernel(const float* __restrict__ gx,
                                                      __nv_bfloat16* __restrict__ cat) {
    __shared__ float sh[8];
    int j = blockIdx.x, tid = threadIdx.x;
    float v = gx[tid * 4096 + j];
    float mean = blockReduceSum256(v, sh) * (1.f / 256.f);
    float d = v - mean;
    float var = blockReduceSum256(d * d, sh) * (1.f / 256.f);
    float y = d * rsqrtf(var + 1e-5f);
    __nv_bfloat16 hi, lo;
    split_bf16(y, hi, lo);
    size_t rb = (size_t)j * 768;
    cat[rb + tid] = hi;
    cat[rb + 256 + tid] = hi;
    cat[rb + 512 + tid] = lo;
}

__global__ void fold_w_kernel(const float* __restrict__ Wk, const float* __restrict__ Wv,
                              const float* __restrict__ lnkw, const float* __restrict__ lnvw,
                              __nv_bfloat16* __restrict__ cat) {
    int idx = blockIdx.x * 256 + threadIdx.x;  // 256*1024
    int oo = idx & 255;
    int c = (idx >> 8) & 255;
    int seg = idx >> 16;  // 0..3 -> [k0,v0,k1,v1]
    int i = seg >> 1, isv = seg & 1;
    const float* W = isv ? Wv : Wk;
    float s = (isv ? lnvw : lnkw)[i * 256 + c];
    float v = s * W[(i * 256 + c) * 256 + oo];
    __nv_bfloat16 hi, lo;
    split_bf16(v, hi, lo);
    int o = seg * 256 + oo;
    size_t rb = (size_t)o * 768;
    cat[rb + c] = hi;
    cat[rb + 256 + c] = lo;
    cat[rb + 512 + c] = hi;
}

__global__ void fold_b_kernel(const float* __restrict__ Wk, const float* __restrict__ Wv,
                              const float* __restrict__ lnkb, const float* __restrict__ lnvb,
                              float* __restrict__ bcat) {
    int wid = threadIdx.x >> 5, lane = threadIdx.x & 31;
    int o = blockIdx.x * 8 + wid;  // grid 128
    int seg = o >> 8, oo = o & 255;
    int i = seg >> 1, isv = seg & 1;
    const float* W = (isv ? Wv : Wk) + i * 256 * 256;
    const float* b = (isv ? lnvb : lnkb) + i * 256;
    float s = 0.f;
#pragma unroll
    for (int t = 0; t < 8; t++) {
        int c = lane + t * 32;
        s += b[c] * W[c * 256 + oo];
    }
#pragma unroll
    for (int off = 16; off; off >>= 1) s += __shfl_xor_sync(0xffffffffu, s, off);
    if (lane == 0) bcat[o] = s;
}

__global__ void wt_split_kernel(const float* __restrict__ W, __nv_bfloat16* __restrict__ cat,
                                int K, int N) {
    int idx = blockIdx.x * 256 + threadIdx.x;  // K*N
    int k = idx / N, n = idx - k * N;
    float v = W[idx];
    __nv_bfloat16 hi, lo;
    split_bf16(v, hi, lo);
    size_t rb = (size_t)n * 3 * K;
    cat[rb + k] = hi;
    cat[rb + K + k] = lo;
    cat[rb + 2 * K + k] = hi;
}

__global__ __launch_bounds__(256) void ln_kernel(const float* __restrict__ in,
                                                 const float* __restrict__ w,
                                                 const float* __restrict__ b,
                                                 float* __restrict__ outF,
                                                 __nv_bfloat16* __restrict__ outCat) {
    __shared__ float sh[8];
    int m = blockIdx.x, tid = threadIdx.x;
    float v = in[m * 256 + tid];
    float mean = blockReduceSum256(v, sh) * (1.f / 256.f);
    float d = v - mean;
    float var = blockReduceSum256(d * d, sh) * (1.f / 256.f);
    float y = d * rsqrtf(var + 1e-5f) * w[tid] + b[tid];
    if (outF) outF[m * 256 + tid] = y;
    if (outCat) {
        __nv_bfloat16 hi, lo;
        split_bf16(y, hi, lo);
        size_t rb = (size_t)m * 768;
        outCat[rb + tid] = hi;
        outCat[rb + 256 + tid] = hi;
        outCat[rb + 512 + tid] = lo;
    }
}

__global__ __launch_bounds__(256) void invnorm_kernel(const float* __restrict__ x,
                                                      float* __restrict__ inv) {
    __shared__ float sh[8];
    int m = blockIdx.x, tid = threadIdx.x;
    float v = x[m * 256 + tid];
    float s2 = blockReduceSum256(v * v, sh);
    if (tid == 0) inv[m] = 1.f / fmaxf(sqrtf(s2), 1e-12f);
}

__global__ void transpose_scale(const float* __restrict__ in, float* __restrict__ out,
                                int R, int Cd, const float* __restrict__ scale) {
    __shared__ float t[32][33];
    int bx = blockIdx.x * 32, by = blockIdx.y * 32;
    int x = threadIdx.x, y0 = threadIdx.y;
    for (int yy = y0; yy < 32; yy += 8) {
        float s = scale ? scale[by + yy] : 1.f;
        t[yy][x] = in[(size_t)(by + yy) * Cd + bx + x] * s;
    }
    __syncthreads();
    for (int yy = y0; yy < 32; yy += 8)
        out[(size_t)(bx + yy) * R + by + x] = t[x][yy];
}

// =================== attention (warp per head) ===================
__global__ __launch_bounds__(256) void attn_kernel(const float* __restrict__ q,
                                                   const float* __restrict__ KV,
                                                   const int* __restrict__ jLarr,
                                                   const int* __restrict__ jRarr,
                                                   int kvOff,
                                                   __nv_bfloat16* __restrict__ acat) {
    int m = blockIdx.x;
    int h = threadIdx.x >> 5;
    int lane = threadIdx.x & 31;
    int jL = jLarr[m], jR = jRarr[m];
    float qv = q[m * 256 + h * 32 + lane] * ATTN_SCALE;
    int base = kvOff + h * 32 + lane;
    float d0 = 0.f, d1 = 0.f;
#pragma unroll
    for (int n = 0; n < 64; n++) {
        int w = (n < 32) ? jL : jR;
        int j = ((n & 31) << 7) + w;
        float p = KV[(size_t)j * 1024 + base] * qv;
        p += __shfl_xor_sync(0xffffffffu, p, 16);
        p += __shfl_xor_sync(0xffffffffu, p, 8);
        p += __shfl_xor_sync(0xffffffffu, p, 4);
        p += __shfl_xor_sync(0xffffffffu, p, 2);
        p += __shfl_xor_sync(0xffffffffu, p, 1);
        if (lane == (n & 31)) { if (n < 32) d0 = p; else d1 = p; }
    }
    float mx = fmaxf(d0, d1);
#pragma unroll
    for (int o = 16; o; o >>= 1) mx = fmaxf(mx, __shfl_xor_sync(0xffffffffu, mx, o));
    float e0 = expf(d0 - mx), e1 = expf(d1 - mx);
    float s = e0 + e1;
#pragma unroll
    for (int o = 16; o; o >>= 1) s += __shfl_xor_sync(0xffffffffu, s, o);
    float invs = 1.f / s;
    float p0 = e0 * invs, p1 = e1 * invs;
    float acc = 0.f;
#pragma unroll
    for (int n = 0; n < 64; n++) {
        float pn = __shfl_sync(0xffffffffu, (n < 32) ? p0 : p1, n & 31);
        int w = (n < 32) ? jL : jR;
        int j = ((n & 31) << 7) + w;
        acc += pn * KV[(size_t)j * 1024 + base + 256];
    }
    int col = h * 32 + lane;
    __nv_bfloat16 hi, lo;
    split_bf16(acc, hi, lo);
    size_t rb = (size_t)m * 768;
    acat[rb + col] = hi;
    acat[rb + 256 + col] = hi;
    acat[rb + 512 + col] = lo;
}

// =================== mma.sync bf16 GEMM ===================
// A: M x Krow bf16 rows; B: N x Krow bf16 rows (col-major B). Tile 128x64, BK=32.
// 8 warps (4 m x 2 n), warp tile 32x32.
// EPI 0: Cf = acc (+bias)  EPI 1: Ccat = split(gelu(acc+bias))  EPI 2: Cf = acc+bias+resid
// SMEM rows padded to 80B (40 bf16) -> conflict-free ldmatrix.
#define ASTRIDE 80
#define STAGE_BYTES 15360  // A: 128*80=10240, B: 64*80=5120
template <int EPI>
__global__ __launch_bounds__(256, 2) void mma_gemm(const __nv_bfloat16* __restrict__ A,
                                                   const __nv_bfloat16* __restrict__ B,
                                                   const float* __restrict__ bias,
                                                   const float* __restrict__ resid,
                                                   float* __restrict__ Cf,
                                                   __nv_bfloat16* __restrict__ Ccat,
                                                   int Krow, int N) {
    __shared__ __align__(16) char sm[2 * STAGE_BYTES];
    uint32_t smBase = smem_u32(sm);
    int tid = threadIdx.x;
    int wid = tid >> 5, lane = tid & 31;
    int wm = wid >> 1, wn = wid & 1;
    int m0 = blockIdx.y << 7, n0 = blockIdx.x << 6;
    int niter = Krow >> 5;

    float acc[2][4][4];
#pragma unroll
    for (int t = 0; t < 2; t++)
#pragma unroll
        for (int j = 0; j < 4; j++)
#pragma unroll
            for (int e = 0; e < 4; e++) acc[t][j][e] = 0.f;

    // per-thread copy coords
    int arow = tid >> 2, ach = tid & 3;              // A: 2 rounds of 64 rows? no: rows tid>>2 + i*64
    // A: 128 rows x 4 chunks = 512 units; 256 threads -> 2 rounds (u = tid + i*256)
    // B: 64 rows x 4 chunks = 256 units -> 1 round

    // ldmatrix addresses
    uint32_t aOff = (uint32_t)((wm * 32 + (lane & 15)) * ASTRIDE + (((lane >> 4) << 3) << 1));
    uint32_t bOff = (uint32_t)((wn * 32 + (lane & 7) + ((lane >> 4) << 3)) * ASTRIDE +
                               ((((lane >> 3) & 1) << 3) << 1));

    // prologue: stage 0
    {
        const __nv_bfloat16* gA = A + (size_t)m0 * Krow;
#pragma unroll
        for (int i = 0; i < 2; i++) {
            int u = tid + (i << 8);
            int row = u >> 2, ch = u & 3;
            cp16(smBase + row * ASTRIDE + ch * 16, gA + (size_t)row * Krow + (ch << 3));
        }
        cp16(smBase + 10240 + arow * ASTRIDE + ach * 16,
             B + (size_t)(n0 + arow) * Krow + (ach << 3));
    }
    cp_commit();

    for (int it = 0; it < niter; ++it) {
        if (it + 1 < niter) {
            int st = (it + 1) & 1;
            int k0 = (it + 1) << 5;
            uint32_t sA = smBase + st * STAGE_BYTES;
            const __nv_bfloat16* gA = A + (size_t)m0 * Krow + k0;
#pragma unroll
            for (int i = 0; i < 2; i++) {
                int u = tid + (i << 8);
                int row = u >> 2, ch = u & 3;
                cp16(sA + row * ASTRIDE + ch * 16, gA + (size_t)row * Krow + (ch << 3));
            }
            cp16(sA + 10240 + arow * ASTRIDE + ach * 16,
                 B + (size_t)(n0 + arow) * Krow + k0 + (ach << 3));
        }
        cp_commit();
        cp_wait1();
        __syncthreads();

        uint32_t aBase = smBase + (it & 1) * STAGE_BYTES + aOff;
        uint32_t bBase = smBase + (it & 1) * STAGE_BYTES + 10240 + bOff;
#pragma unroll
        for (int ks = 0; ks < 2; ks++) {
            uint32_t a[2][4], b[2][4];
            ldsm4(a[0], aBase + ks * 32);
            ldsm4(a[1], aBase + 16 * ASTRIDE + ks * 32);
            ldsm4(b[0], bBase + ks * 32);
            ldsm4(b[1], bBase + 16 * ASTRIDE + ks * 32);
#pragma unroll
            for (int t = 0; t < 2; t++) {
#pragma unroll
                for (int j = 0; j < 4; j++) {
                    uint32_t b0 = b[j >> 1][(j & 1) ? 2 : 0];
                    uint32_t b1 = b[j >> 1][(j & 1) ? 3 : 1];
                    mma16816(acc[t][j], a[t], b0, b1);
                }
            }
        }
        __syncthreads();
    }

    // epilogue
#pragma unroll
    for (int t = 0; t < 2; t++) {
        int row0 = m0 + wm * 32 + t * 16 + (lane >> 2);
        int row1 = row0 + 8;
#pragma unroll
        for (int j = 0; j < 4; j++) {
            int col = n0 + wn * 32 + j * 8 + ((lane & 3) << 1);
            float v0 = acc[t][j][0], v1 = acc[t][j][1];
            float v2 = acc[t][j][2], v3 = acc[t][j][3];
            if (EPI != 0 || bias) {
                float b0 = bias[col], b1 = bias[col + 1];
                v0 += b0; v1 += b1; v2 += b0; v3 += b1;
            }
            if (EPI == 1) {
                v0 = 0.5f * v0 * (1.f + erff(v0 * 0.70710678118654752f));
                v1 = 0.5f * v1 * (1.f + erff(v1 * 0.70710678118654752f));
                v2 = 0.5f * v2 * (1.f + erff(v2 * 0.70710678118654752f));
                v3 = 0.5f * v3 * (1.f + erff(v3 * 0.70710678118654752f));
                __nv_bfloat16 h0, l0, h1, l1, h2, l2, h3, l3;
                split_bf16(v0, h0, l0);
                split_bf16(v1, h1, l1);
                split_bf16(v2, h2, l2);
                split_bf16(v3, h3, l3);
                size_t rb0 = (size_t)row0 * 3 * N + col;
                size_t rb1 = (size_t)row1 * 3 * N + col;
                *(__nv_bfloat162*)(Ccat + rb0) = __nv_bfloat162(h0, h1);
                *(__nv_bfloat162*)(Ccat + rb0 + N) = __nv_bfloat162(h0, h1);
                *(__nv_bfloat162*)(Ccat + rb0 + 2 * N) = __nv_bfloat162(l0, l1);
                *(__nv_bfloat162*)(Ccat + rb1) = __nv_bfloat162(h2, h3);
                *(__nv_bfloat162*)(Ccat + rb1 + N) = __nv_bfloat162(h2, h3);
                *(__nv_bfloat162*)(Ccat + rb1 + 2 * N) = __nv_bfloat162(l2, l3);
            } else {
                if (EPI == 2) {
                    float2 r0 = *(const float2*)(resid + (size_t)row0 * N + col);
                    float2 r1 = *(const float2*)(resid + (size_t)row1 * N + col);
                    v0 += r0.x; v1 += r0.y; v2 += r1.x; v3 += r1.y;
                }
                *(float2*)(Cf + (size_t)row0 * N + col) = make_float2(v0, v1);
                *(float2*)(Cf + (size_t)row1 * N + col) = make_float2(v2, v3);
            }
        }
    }
}

// =================== host launch ===================
extern "C" void kernel_launch(void* const* d_in, const int* in_sizes, int n_in,
                              void* d_out, int out_size) {
    (void)in_sizes; (void)n_in; (void)out_size;
    const float* grd2sat = (const float*)d_in[0];
    const float* grd_x   = (const float*)d_in[1];
    const float* u       = (const float*)d_in[2];
    const float* ln_q_w  = (const float*)d_in[3];
    const float* ln_q_b  = (const float*)d_in[4];
    const float* ln_k_w  = (const float*)d_in[5];
    const float* ln_k_b  = (const float*)d_in[6];
    const float* ln_v_w  = (const float*)d_in[7];
    const float* ln_v_b  = (const float*)d_in[8];
    const float* Wq      = (const float*)d_in[9];
    const float* Wk      = (const float*)d_in[10];
    const float* Wv      = (const float*)d_in[11];
    const float* Wproj   = (const float*)d_in[12];
    const float* bproj   = (const float*)d_in[13];
    const float* ln_pre_w  = (const float*)d_in[14];
    const float* ln_pre_b  = (const float*)d_in[15];
    const float* Wm1     = (const float*)d_in[16];
    const float* bm1     = (const float*)d_in[17];
    const float* Wm2     = (const float*)d_in[18];
    const float* bm2     = (const float*)d_in[19];
    const float* ln_post_w = (const float*)d_in[20];
    const float* ln_post_b = (const float*)d_in[21];
    float* out = (float*)d_out;

    __nv_bfloat16 *Xncat, *Wkvcat, *tcat, *acat, *z2cat, *hcat, *Wqcat, *Wpcat, *Wm1cat, *Wm2cat;
    float *bcat, *KV, *x, *q, *z1, *z2, *z3, *inv;
    int *jL, *jR;
    cudaGetSymbolAddress((void**)&Xncat, g_Xncat);
    cudaGetSymbolAddress((void**)&Wkvcat, g_Wkvcat);
    cudaGetSymbolAddress((void**)&bcat, g_bcat);
    cudaGetSymbolAddress((void**)&KV, g_KV);
    cudaGetSymbolAddress((void**)&x, g_x);
    cudaGetSymbolAddress((void**)&tcat, g_tcat);
    cudaGetSymbolAddress((void**)&q, g_q);
    cudaGetSymbolAddress((void**)&acat, g_acat);
    cudaGetSymbolAddress((void**)&z1, g_z1);
    cudaGetSymbolAddress((void**)&z2, g_z2);
    cudaGetSymbolAddress((void**)&z2cat, g_z2cat);
    cudaGetSymbolAddress((void**)&hcat, g_hcat);
    cudaGetSymbolAddress((void**)&z3, g_z3);
    cudaGetSymbolAddress((void**)&Wqcat, g_Wqcat);
    cudaGetSymbolAddress((void**)&Wpcat, g_Wpcat);
    cudaGetSymbolAddress((void**)&Wm1cat, g_Wm1cat);
    cudaGetSymbolAddress((void**)&Wm2cat, g_Wm2cat);
    cudaGetSymbolAddress((void**)&inv, g_inv);
    cudaGetSymbolAddress((void**)&jL, g_jL);
    cudaGetSymbolAddress((void**)&jR, g_jR);

    idx_kernel<<<16, 256>>>(u, jL, jR);
    colnorm_kernel<<<4096, 256>>>(grd_x, Xncat);
    fold_w_kernel<<<1024, 256>>>(Wk, Wv, ln_k_w, ln_v_w, Wkvcat);
    fold_b_kernel<<<128, 256>>>(Wk, Wv, ln_k_b, ln_v_b, bcat);
    // KV = Xn @ Wcat + bcat : (4096 x 1024)
    mma_gemm<0><<<dim3(16, 32), 256>>>(Xncat, Wkvcat, bcat, nullptr, KV, nullptr, 768, 1024);
    transpose_scale<<<dim3(128, 8), dim3(32, 8)>>>(grd2sat, x, 256, 4096, nullptr);

    for (int i = 0; i < 2; i++) {
        wt_split_kernel<<<256, 256>>>(Wq + i * 256 * 256, Wqcat, 256, 256);
        wt_split_kernel<<<256, 256>>>(Wproj + i * 256 * 256, Wpcat, 256, 256);
        wt_split_kernel<<<512, 256>>>(Wm1 + i * 256 * 512, Wm1cat, 256, 512);
        wt_split_kernel<<<512, 256>>>(Wm2 + i * 512 * 256, Wm2cat, 512, 256);

        ln_kernel<<<4096, 256>>>(x, ln_q_w + i * 256, ln_q_b + i * 256, nullptr, tcat);
        mma_gemm<0><<<dim3(4, 32), 256>>>(tcat, Wqcat, nullptr, nullptr, q, nullptr, 768, 256);
        attn_kernel<<<4096, 256>>>(q, KV, jL, jR, i * 512, acat);
        mma_gemm<0><<<dim3(4, 32), 256>>>(acat, Wpcat, bproj + i * 256, nullptr, z1, nullptr,
                                          768, 256);
        ln_kernel<<<4096, 256>>>(z1, ln_pre_w + i * 256, ln_pre_b + i * 256, z2, z2cat);
        mma_gemm<1><<<dim3(8, 32), 256>>>(z2cat, Wm1cat, bm1 + i * 512, nullptr, nullptr,
                                          hcat, 768, 512);
        mma_gemm<2><<<dim3(4, 32), 256>>>(hcat, Wm2cat, bm2 + i * 256, z2, z3, nullptr,
                                          1536, 256);
        ln_kernel<<<4096, 256>>>(z3, ln_post_w + i * 256, ln_post_b + i * 256, x, nullptr);
    }

    invnorm_kernel<<<4096, 256>>>(x, inv);
    transpose_scale<<<dim3(8, 128), dim3(32, 8)>>>(x, out, 4096, 256, inv);
}